// round 1
// baseline (speedup 1.0000x reference)
#include <cuda_runtime.h>
#include <math.h>

// Shapes (fixed)
#define DIMN   1024
#define BB     2
#define TT     512
#define HH     8
#define HKD    128
#define NROWS  (BB*TT)          // 1024
#define QSCALE 0.08838834764831845f   // 128^-0.5
#define GNORM  0.0625f                // 1/16

// Scratch (no cudaMalloc allowed)
__device__ float g_q [NROWS*DIMN];
__device__ float g_k [NROWS*DIMN];
__device__ float g_v [NROWS*DIMN];
__device__ float g_g [NROWS*DIMN];
__device__ float g_gk[NROWS*DIMN];
__device__ float g_t1[NROWS*16];
__device__ float g_o [NROWS*DIMN];
__device__ float g_on[NROWS*DIMN];

// ---------------------------------------------------------------------------
// Tiled SGEMM body: C[1024,1024] = alpha * A[1024,1024] @ W[1024,1024]
// BM=128, BN=64, BK=16, 256 threads, thread tile 8x4.
// ---------------------------------------------------------------------------
__device__ __forceinline__ void gemm_tile(const float* __restrict__ A,
                                          const float* __restrict__ W,
                                          float* __restrict__ C, float alpha)
{
    __shared__ float As[16][132];   // padded, transposed A tile
    __shared__ float Bs[16][64];

    const int tid  = threadIdx.x;
    const int brow = blockIdx.y * 128;
    const int bcol = blockIdx.x * 64;
    const int trow = (tid >> 4) << 3;   // 0..120 step 8
    const int tcol = (tid & 15) << 2;   // 0..60  step 4

    float acc[8][4];
#pragma unroll
    for (int i = 0; i < 8; i++)
#pragma unroll
        for (int j = 0; j < 4; j++) acc[i][j] = 0.f;

    for (int kt = 0; kt < 1024; kt += 16) {
        // Load A tile (128x16) as 2 float4 per thread, transpose into As
#pragma unroll
        for (int u = 0; u < 2; u++) {
            int f    = tid + (u << 8);
            int arow = f >> 2;
            int acol = (f & 3) << 2;
            float4 av = *(const float4*)(A + (brow + arow) * 1024 + kt + acol);
            As[acol + 0][arow] = av.x;
            As[acol + 1][arow] = av.y;
            As[acol + 2][arow] = av.z;
            As[acol + 3][arow] = av.w;
        }
        // Load B tile (16x64), 1 float4 per thread
        {
            int brw = tid >> 4;
            int bc  = (tid & 15) << 2;
            *(float4*)(&Bs[brw][bc]) =
                *(const float4*)(W + (kt + brw) * 1024 + bcol + bc);
        }
        __syncthreads();

#pragma unroll
        for (int k = 0; k < 16; k++) {
            float4 a0 = *(const float4*)(&As[k][trow]);
            float4 a1 = *(const float4*)(&As[k][trow + 4]);
            float4 b0 = *(const float4*)(&Bs[k][tcol]);
            float ar[8] = {a0.x, a0.y, a0.z, a0.w, a1.x, a1.y, a1.z, a1.w};
            float br[4] = {b0.x, b0.y, b0.z, b0.w};
#pragma unroll
            for (int i = 0; i < 8; i++)
#pragma unroll
                for (int j = 0; j < 4; j++)
                    acc[i][j] = fmaf(ar[i], br[j], acc[i][j]);
        }
        __syncthreads();
    }

#pragma unroll
    for (int i = 0; i < 8; i++) {
        float4 o;
        o.x = acc[i][0] * alpha;
        o.y = acc[i][1] * alpha;
        o.z = acc[i][2] * alpha;
        o.w = acc[i][3] * alpha;
        *(float4*)(C + (brow + trow + i) * 1024 + bcol + tcol) = o;
    }
}

// 4 projections fused via blockIdx.z
__global__ __launch_bounds__(256) void proj4_kernel(
    const float* __restrict__ x,
    const float* __restrict__ Wq, const float* __restrict__ Wk,
    const float* __restrict__ Wv, const float* __restrict__ Wg)
{
    const float* W; float* O; float alpha = 1.f;
    switch (blockIdx.z) {
        case 0:  W = Wq; O = g_q; alpha = QSCALE; break;
        case 1:  W = Wk; O = g_k; break;
        case 2:  W = Wv; O = g_v; break;
        default: W = Wg; O = g_g; break;
    }
    gemm_tile(x, W, O, alpha);
}

__global__ __launch_bounds__(256) void out_gemm_kernel(
    const float* __restrict__ Wo, float* __restrict__ out)
{
    gemm_tile(g_on, Wo, out, 1.f);
}

// ---------------------------------------------------------------------------
// Low-rank gate: t1 = x @ Wgk1  (1024x1024 @ 1024x16)
// ---------------------------------------------------------------------------
__global__ __launch_bounds__(256) void lowrank1_kernel(
    const float* __restrict__ x, const float* __restrict__ Wgk1)
{
    int r   = threadIdx.x >> 4;
    int c   = threadIdx.x & 15;
    int row = blockIdx.x * 16 + r;
    const float* xr = x + row * 1024;
    float acc = 0.f;
#pragma unroll 8
    for (int k = 0; k < 1024; k++)
        acc = fmaf(xr[k], Wgk1[k * 16 + c], acc);
    g_t1[row * 16 + c] = acc;
}

// gk = logsigmoid(t1 @ Wgk2 + b) / 16   (1024x16 @ 16x1024)
__global__ __launch_bounds__(256) void gk_kernel(
    const float* __restrict__ Wgk2, const float* __restrict__ bgk2)
{
    __shared__ float sT[16];
    int m = blockIdx.x >> 2;
    int n = ((blockIdx.x & 3) << 8) + threadIdx.x;
    if (threadIdx.x < 16) sT[threadIdx.x] = g_t1[m * 16 + threadIdx.x];
    __syncthreads();
    float acc = bgk2[n];
#pragma unroll
    for (int j = 0; j < 16; j++)
        acc = fmaf(sT[j], Wgk2[j * 1024 + n], acc);
    // stable logsigmoid
    float ls = fminf(acc, 0.f) - log1pf(__expf(-fabsf(acc)));
    g_gk[m * 1024 + n] = ls * GNORM;
}

// ---------------------------------------------------------------------------
// Sequential GLA scan. One block per (b,h). 256 threads: v = tid&127,
// k-half = tid>>7. Each thread keeps 64 state floats in registers.
//   S_t = S_{t-1} * exp(gk_t)[k] + k_t[k] * v_t[v];  o_t[v] = sum_k q_t[k]*S
// ---------------------------------------------------------------------------
__global__ __launch_bounds__(256) void scan_kernel()
{
    __shared__ float4 sQKE[128];   // (exp(gk), k, q, -)
    __shared__ float  sPart[128];

    const int bh  = blockIdx.x;       // 0..15
    const int b   = bh >> 3;
    const int h   = bh & 7;
    const int tid = threadIdx.x;
    const int v   = tid & 127;
    const int kh  = tid >> 7;
    const int kb  = kh << 6;

    float S[64];
#pragma unroll
    for (int i = 0; i < 64; i++) S[i] = 0.f;

    for (int t = 0; t < TT; t++) {
        const int rowbase = ((b * TT + t) * HH + h) * HKD;
        if (kh == 0) {
            float e  = __expf(g_gk[rowbase + v]);
            float kk = g_k[rowbase + v];
            float qq = g_q[rowbase + v];
            sQKE[v] = make_float4(e, kk, qq, 0.f);
        }
        float vt = g_v[rowbase + v];
        __syncthreads();

        float a0 = 0.f, a1 = 0.f, a2 = 0.f, a3 = 0.f;
#pragma unroll
        for (int i = 0; i < 64; i += 4) {
            float4 w0 = sQKE[kb + i + 0];
            S[i + 0] = fmaf(S[i + 0], w0.x, w0.y * vt);
            a0 = fmaf(w0.z, S[i + 0], a0);
            float4 w1 = sQKE[kb + i + 1];
            S[i + 1] = fmaf(S[i + 1], w1.x, w1.y * vt);
            a1 = fmaf(w1.z, S[i + 1], a1);
            float4 w2 = sQKE[kb + i + 2];
            S[i + 2] = fmaf(S[i + 2], w2.x, w2.y * vt);
            a2 = fmaf(w2.z, S[i + 2], a2);
            float4 w3 = sQKE[kb + i + 3];
            S[i + 3] = fmaf(S[i + 3], w3.x, w3.y * vt);
            a3 = fmaf(w3.z, S[i + 3], a3);
        }
        float acc = (a0 + a1) + (a2 + a3);

        if (kh == 1) sPart[v] = acc;
        __syncthreads();
        if (kh == 0) g_o[rowbase + v] = acc + sPart[v];
        __syncthreads();   // protect sQKE/sPart before next step overwrites
    }
}

// ---------------------------------------------------------------------------
// Gated RMSNorm: o = o * rsqrt(mean(o^2)+eps) * w * (g * sigmoid(g))
// One block per (b,t,h) row of 128.
// ---------------------------------------------------------------------------
__global__ __launch_bounds__(128) void norm_kernel(
    const float* __restrict__ g_norm_w)
{
    const int row = blockIdx.x;          // 0..8191
    const int v   = threadIdx.x;
    const int idx = row * 128 + v;

    float ov = g_o[idx];
    float gv = g_g[idx];

    float ss = ov * ov;
#pragma unroll
    for (int off = 16; off; off >>= 1)
        ss += __shfl_xor_sync(0xffffffffu, ss, off);

    __shared__ float sW[4];
    if ((v & 31) == 0) sW[v >> 5] = ss;
    __syncthreads();
    float tot = sW[0] + sW[1] + sW[2] + sW[3];

    float rms = rsqrtf(tot * (1.f / 128.f) + 1e-5f);
    float sw  = gv / (1.f + __expf(-gv));   // g * sigmoid(g)
    g_on[idx] = ov * rms * g_norm_w[v] * sw;
}

// ---------------------------------------------------------------------------
extern "C" void kernel_launch(void* const* d_in, const int* in_sizes, int n_in,
                              void* d_out, int out_size)
{
    const float* x        = (const float*)d_in[0];
    const float* Wq       = (const float*)d_in[1];
    const float* Wk       = (const float*)d_in[2];
    const float* Wv       = (const float*)d_in[3];
    const float* Wg       = (const float*)d_in[4];
    const float* Wgk1     = (const float*)d_in[5];
    const float* Wgk2     = (const float*)d_in[6];
    const float* bgk2     = (const float*)d_in[7];
    const float* g_norm_w = (const float*)d_in[8];
    const float* Wo       = (const float*)d_in[9];
    float* out = (float*)d_out;

    dim3 gp(16, 8, 4);                       // 1024/64 x 1024/128 x 4 proj
    proj4_kernel<<<gp, 256>>>(x, Wq, Wk, Wv, Wg);
    lowrank1_kernel<<<64, 256>>>(x, Wgk1);
    gk_kernel<<<4096, 256>>>(Wgk2, bgk2);
    scan_kernel<<<16, 256>>>();
    norm_kernel<<<NROWS * HH, 128>>>(g_norm_w);
    dim3 go(16, 8, 1);
    out_gemm_kernel<<<go, 256>>>(Wo, out);
}

// round 2
// speedup vs baseline: 1.8204x; 1.8204x over previous
#include <cuda_runtime.h>
#include <math.h>

// Shapes (fixed)
#define DIMN   1024
#define BB     2
#define TT     512
#define HH     8
#define HKD    128
#define NROWS  (BB*TT)          // 1024
#define CH     64               // chunk length
#define NC     (TT/CH)          // 8 chunks
#define QSCALE 0.08838834764831845f   // 128^-0.5
#define GNORM  0.0625f                // 1/16

// Scratch (no cudaMalloc allowed)
__device__ float g_q [NROWS*DIMN];
__device__ float g_k [NROWS*DIMN];
__device__ float g_v [NROWS*DIMN];
__device__ float g_g [NROWS*DIMN];
__device__ float g_gk[NROWS*DIMN];
__device__ float g_t1[NROWS*16];
__device__ float g_on[NROWS*DIMN];
// chunked-GLA scratch
__device__ float g_qg[NROWS*DIMN];            // q~ = q * e^{b_t}
__device__ float g_kd[NROWS*DIMN];            // k^ = k * e^{-b_t}
__device__ float g_kr[NROWS*DIMN];            // k~ = k * e^{G_C - b_t}
__device__ float g_kv[16*NC*HKD*HKD];         // per-chunk K~^T V
__device__ float g_S [16*NC*HKD*HKD];         // state at chunk START
__device__ float g_dc[16*NC*HKD];             // e^{G_C}

// ---------------------------------------------------------------------------
// Tiled SGEMM body: C[1024,1024] = alpha * A[1024,1024] @ W[1024,1024]
// ---------------------------------------------------------------------------
__device__ __forceinline__ void gemm_tile(const float* __restrict__ A,
                                          const float* __restrict__ W,
                                          float* __restrict__ C, float alpha)
{
    __shared__ float As[16][132];
    __shared__ float Bs[16][64];

    const int tid  = threadIdx.x;
    const int brow = blockIdx.y * 128;
    const int bcol = blockIdx.x * 64;
    const int trow = (tid >> 4) << 3;
    const int tcol = (tid & 15) << 2;

    float acc[8][4];
#pragma unroll
    for (int i = 0; i < 8; i++)
#pragma unroll
        for (int j = 0; j < 4; j++) acc[i][j] = 0.f;

    for (int kt = 0; kt < 1024; kt += 16) {
#pragma unroll
        for (int u = 0; u < 2; u++) {
            int f    = tid + (u << 8);
            int arow = f >> 2;
            int acol = (f & 3) << 2;
            float4 av = *(const float4*)(A + (brow + arow) * 1024 + kt + acol);
            As[acol + 0][arow] = av.x;
            As[acol + 1][arow] = av.y;
            As[acol + 2][arow] = av.z;
            As[acol + 3][arow] = av.w;
        }
        {
            int brw = tid >> 4;
            int bc  = (tid & 15) << 2;
            *(float4*)(&Bs[brw][bc]) =
                *(const float4*)(W + (kt + brw) * 1024 + bcol + bc);
        }
        __syncthreads();

#pragma unroll
        for (int k = 0; k < 16; k++) {
            float4 a0 = *(const float4*)(&As[k][trow]);
            float4 a1 = *(const float4*)(&As[k][trow + 4]);
            float4 b0 = *(const float4*)(&Bs[k][tcol]);
            float ar[8] = {a0.x, a0.y, a0.z, a0.w, a1.x, a1.y, a1.z, a1.w};
            float br[4] = {b0.x, b0.y, b0.z, b0.w};
#pragma unroll
            for (int i = 0; i < 8; i++)
#pragma unroll
                for (int j = 0; j < 4; j++)
                    acc[i][j] = fmaf(ar[i], br[j], acc[i][j]);
        }
        __syncthreads();
    }

#pragma unroll
    for (int i = 0; i < 8; i++) {
        float4 o;
        o.x = acc[i][0] * alpha;
        o.y = acc[i][1] * alpha;
        o.z = acc[i][2] * alpha;
        o.w = acc[i][3] * alpha;
        *(float4*)(C + (brow + trow + i) * 1024 + bcol + tcol) = o;
    }
}

__global__ __launch_bounds__(256) void proj4_kernel(
    const float* __restrict__ x,
    const float* __restrict__ Wq, const float* __restrict__ Wk,
    const float* __restrict__ Wv, const float* __restrict__ Wg)
{
    const float* W; float* O; float alpha = 1.f;
    switch (blockIdx.z) {
        case 0:  W = Wq; O = g_q; alpha = QSCALE; break;
        case 1:  W = Wk; O = g_k; break;
        case 2:  W = Wv; O = g_v; break;
        default: W = Wg; O = g_g; break;
    }
    gemm_tile(x, W, O, alpha);
}

__global__ __launch_bounds__(256) void out_gemm_kernel(
    const float* __restrict__ Wo, float* __restrict__ out)
{
    gemm_tile(g_on, Wo, out, 1.f);
}

// ---------------------------------------------------------------------------
// Low-rank gate path
// ---------------------------------------------------------------------------
__global__ __launch_bounds__(256) void lowrank1_kernel(
    const float* __restrict__ x, const float* __restrict__ Wgk1)
{
    int r   = threadIdx.x >> 4;
    int c   = threadIdx.x & 15;
    int row = blockIdx.x * 16 + r;
    const float* xr = x + row * 1024;
    float acc = 0.f;
#pragma unroll 8
    for (int k = 0; k < 1024; k++)
        acc = fmaf(xr[k], Wgk1[k * 16 + c], acc);
    g_t1[row * 16 + c] = acc;
}

__global__ __launch_bounds__(256) void gk_kernel(
    const float* __restrict__ Wgk2, const float* __restrict__ bgk2)
{
    __shared__ float sT[16];
    int m = blockIdx.x >> 2;
    int n = ((blockIdx.x & 3) << 8) + threadIdx.x;
    if (threadIdx.x < 16) sT[threadIdx.x] = g_t1[m * 16 + threadIdx.x];
    __syncthreads();
    float acc = bgk2[n];
#pragma unroll
    for (int j = 0; j < 16; j++)
        acc = fmaf(sT[j], Wgk2[j * 1024 + n], acc);
    float ls = fminf(acc, 0.f) - log1pf(__expf(-fabsf(acc)));
    g_gk[m * 1024 + n] = ls * GNORM;
}

// ---------------------------------------------------------------------------
// Chunked GLA
// row index helper: global row offset for (b, h, t) -> float index
// ---------------------------------------------------------------------------
__device__ __forceinline__ int row_off(int b, int h, int t)
{
    return (((b * TT + t) * HH + h) << 7);
}

// prep: per (bh, chunk, channel) compute gate cumsums and scaled q/k copies
__global__ __launch_bounds__(128) void prep_kernel()
{
    const int bhc = blockIdx.x;        // bh*NC + c
    const int bh  = bhc >> 3, c0 = bhc & 7;
    const int b   = bh >> 3,  h  = bh & 7;
    const int ch  = threadIdx.x;
    const int tbase = c0 * CH;

    float tot = 0.f;
#pragma unroll 8
    for (int s = 0; s < CH; s++)
        tot += g_gk[row_off(b, h, tbase + s) + ch];

    float bacc = 0.f;
#pragma unroll 4
    for (int s = 0; s < CH; s++) {
        int r = row_off(b, h, tbase + s) + ch;
        bacc += g_gk[r];
        float q = g_q[r], k = g_k[r];
        g_qg[r] = q * __expf(bacc);
        g_kd[r] = k * __expf(-bacc);
        g_kr[r] = k * __expf(tot - bacc);
    }
    g_dc[bhc * 128 + ch] = __expf(tot);
}

// chunk_kv: KV_c[128][128] = sum_s k~_s^T v_s   (contraction over s = 64)
__global__ __launch_bounds__(256) void chunk_kv_kernel()
{
    const int bhc = blockIdx.x;
    const int bh  = bhc >> 3, c0 = bhc & 7;
    const int b   = bh >> 3,  h  = bh & 7;
    const int tid = threadIdx.x;
    const int tr  = tid >> 4, tc = tid & 15;
    const int kr0 = tr << 3, vc0 = tc << 3;
    const int tbase = c0 * CH;

    __shared__ float sK[16][128];
    __shared__ float sV[16][128];

    float acc[8][8];
#pragma unroll
    for (int i = 0; i < 8; i++)
#pragma unroll
        for (int j = 0; j < 8; j++) acc[i][j] = 0.f;

    for (int st = 0; st < 4; st++) {
#pragma unroll
        for (int u = 0; u < 2; u++) {
            int f  = tid + (u << 8);
            int sr = f >> 5;
            int sc = (f & 31) << 2;
            int r  = row_off(b, h, tbase + st * 16 + sr) + sc;
            *(float4*)&sK[sr][sc] = *(const float4*)(g_kr + r);
            *(float4*)&sV[sr][sc] = *(const float4*)(g_v + r);
        }
        __syncthreads();
#pragma unroll
        for (int ss = 0; ss < 16; ss++) {
            float4 k0 = *(const float4*)&sK[ss][kr0];
            float4 k1 = *(const float4*)&sK[ss][kr0 + 4];
            float4 v0 = *(const float4*)&sV[ss][vc0];
            float4 v1 = *(const float4*)&sV[ss][vc0 + 4];
            float kr[8] = {k0.x,k0.y,k0.z,k0.w,k1.x,k1.y,k1.z,k1.w};
            float vr[8] = {v0.x,v0.y,v0.z,v0.w,v1.x,v1.y,v1.z,v1.w};
#pragma unroll
            for (int i = 0; i < 8; i++)
#pragma unroll
                for (int j = 0; j < 8; j++)
                    acc[i][j] = fmaf(kr[i], vr[j], acc[i][j]);
        }
        __syncthreads();
    }

    float* dst = g_kv + (size_t)bhc * 16384;
#pragma unroll
    for (int i = 0; i < 8; i++) {
        *(float4*)(dst + (kr0 + i) * 128 + vc0)     = make_float4(acc[i][0],acc[i][1],acc[i][2],acc[i][3]);
        *(float4*)(dst + (kr0 + i) * 128 + vc0 + 4) = make_float4(acc[i][4],acc[i][5],acc[i][6],acc[i][7]);
    }
}

// state scan: sequential over 8 chunks, parallel over 16 bh blocks.
// Writes S BEFORE applying chunk c (state at chunk start).
__global__ __launch_bounds__(256) void state_scan_kernel()
{
    const int bh  = blockIdx.x;
    const int tid = threadIdx.x;
    const int k   = tid >> 1;

    float S[64];
#pragma unroll
    for (int i = 0; i < 64; i++) S[i] = 0.f;

    for (int c = 0; c < NC; c++) {
        const size_t base = ((size_t)(bh * NC + c)) * 16384 + (size_t)tid * 64;
        const float d = g_dc[(bh * NC + c) * 128 + k];
#pragma unroll
        for (int i4 = 0; i4 < 16; i4++) {
            *(float4*)(g_S + base + i4 * 4) =
                make_float4(S[i4*4], S[i4*4+1], S[i4*4+2], S[i4*4+3]);
            float4 kv = *(const float4*)(g_kv + base + i4 * 4);
            S[i4*4+0] = fmaf(S[i4*4+0], d, kv.x);
            S[i4*4+1] = fmaf(S[i4*4+1], d, kv.y);
            S[i4*4+2] = fmaf(S[i4*4+2], d, kv.z);
            S[i4*4+3] = fmaf(S[i4*4+3], d, kv.w);
        }
    }
}

// chunk_out: o = q~ @ S_c + tril(q~ @ k^^T) @ V, fused gated RMSNorm -> g_on
__global__ __launch_bounds__(256) void chunk_out_kernel(
    const float* __restrict__ g_norm_w)
{
    const int bhc = blockIdx.x;
    const int bh  = bhc >> 3, c0 = bhc & 7;
    const int b   = bh >> 3,  h  = bh & 7;
    const int tid = threadIdx.x;
    const int tr  = tid >> 4, tc = tid & 15;
    const int t0  = tr << 2;        // 4 t-rows per thread
    const int v0  = tc << 3;        // 8 v-cols per thread
    const int tbase = c0 * CH;

    __shared__ float sQ [16][68];   // [k][t] transposed
    __shared__ float sKd[16][68];   // [k][s] transposed
    __shared__ float sS [16][128];  // [k][v]
    __shared__ float sA [64][68];   // [t][s]
    __shared__ float sV [16][128];  // [s][v]

    float o[4][8];
    float a2[4][4];
#pragma unroll
    for (int i = 0; i < 4; i++) {
#pragma unroll
        for (int j = 0; j < 8; j++) o[i][j] = 0.f;
#pragma unroll
        for (int j = 0; j < 4; j++) a2[i][j] = 0.f;
    }

    const size_t Sbase = (size_t)bhc * 16384;

    // ---- contraction over k: o_inter and A simultaneously ----
    for (int k0 = 0; k0 < 128; k0 += 16) {
        {
            int tt = tid >> 2;
            int c4 = (tid & 3) << 2;
            int r  = row_off(b, h, tbase + tt) + k0 + c4;
            float4 qv = *(const float4*)(g_qg + r);
            sQ[c4+0][tt] = qv.x; sQ[c4+1][tt] = qv.y;
            sQ[c4+2][tt] = qv.z; sQ[c4+3][tt] = qv.w;
            float4 kv = *(const float4*)(g_kd + r);
            sKd[c4+0][tt] = kv.x; sKd[c4+1][tt] = kv.y;
            sKd[c4+2][tt] = kv.z; sKd[c4+3][tt] = kv.w;
        }
#pragma unroll
        for (int u = 0; u < 2; u++) {
            int f  = tid + (u << 8);
            int sr = f >> 5;
            int sc = (f & 31) << 2;
            *(float4*)&sS[sr][sc] =
                *(const float4*)(g_S + Sbase + (k0 + sr) * 128 + sc);
        }
        __syncthreads();

#pragma unroll
        for (int kk = 0; kk < 16; kk++) {
            float4 q4  = *(const float4*)&sQ[kk][t0];
            float4 s0  = *(const float4*)&sS[kk][v0];
            float4 s1  = *(const float4*)&sS[kk][v0 + 4];
            float4 kd4 = *(const float4*)&sKd[kk][tc << 2];
            float qr[4] = {q4.x, q4.y, q4.z, q4.w};
            float sr_[8] = {s0.x,s0.y,s0.z,s0.w,s1.x,s1.y,s1.z,s1.w};
            float kr[4] = {kd4.x,kd4.y,kd4.z,kd4.w};
#pragma unroll
            for (int i = 0; i < 4; i++) {
#pragma unroll
                for (int j = 0; j < 8; j++)
                    o[i][j] = fmaf(qr[i], sr_[j], o[i][j]);
#pragma unroll
                for (int j = 0; j < 4; j++)
                    a2[i][j] = fmaf(qr[i], kr[j], a2[i][j]);
            }
        }
        __syncthreads();
    }

    // ---- causal mask, stash A ----
#pragma unroll
    for (int i = 0; i < 4; i++) {
        int t = t0 + i;
#pragma unroll
        for (int j = 0; j < 4; j++) {
            int s = (tc << 2) + j;
            sA[t][s] = (s <= t) ? a2[i][j] : 0.f;
        }
    }
    __syncthreads();

    // ---- o_intra = A @ V (contraction over s) ----
    for (int st = 0; st < 4; st++) {
#pragma unroll
        for (int u = 0; u < 2; u++) {
            int f  = tid + (u << 8);
            int sr = f >> 5;
            int sc = (f & 31) << 2;
            int r  = row_off(b, h, tbase + st * 16 + sr) + sc;
            *(float4*)&sV[sr][sc] = *(const float4*)(g_v + r);
        }
        __syncthreads();
#pragma unroll
        for (int ss = 0; ss < 16; ss++) {
            int s = st * 16 + ss;
            float a[4];
#pragma unroll
            for (int i = 0; i < 4; i++) a[i] = sA[t0 + i][s];
            float4 vv0 = *(const float4*)&sV[ss][v0];
            float4 vv1 = *(const float4*)&sV[ss][v0 + 4];
            float vr[8] = {vv0.x,vv0.y,vv0.z,vv0.w,vv1.x,vv1.y,vv1.z,vv1.w};
#pragma unroll
            for (int i = 0; i < 4; i++)
#pragma unroll
                for (int j = 0; j < 8; j++)
                    o[i][j] = fmaf(a[i], vr[j], o[i][j]);
        }
        __syncthreads();
    }

    // ---- fused gated RMSNorm (row = full 128 v within the 16-tc group) ----
    float4 w0 = *(const float4*)(g_norm_w + v0);
    float4 w1 = *(const float4*)(g_norm_w + v0 + 4);
    float wr[8] = {w0.x,w0.y,w0.z,w0.w,w1.x,w1.y,w1.z,w1.w};

#pragma unroll
    for (int i = 0; i < 4; i++) {
        float ss = 0.f;
#pragma unroll
        for (int j = 0; j < 8; j++) ss = fmaf(o[i][j], o[i][j], ss);
#pragma unroll
        for (int off = 1; off < 16; off <<= 1)
            ss += __shfl_xor_sync(0xffffffffu, ss, off);
        float rms = rsqrtf(ss * (1.f / 128.f) + 1e-5f);

        int r = row_off(b, h, tbase + t0 + i);
        float4 gg0 = *(const float4*)(g_g + r + v0);
        float4 gg1 = *(const float4*)(g_g + r + v0 + 4);
        float gr[8] = {gg0.x,gg0.y,gg0.z,gg0.w,gg1.x,gg1.y,gg1.z,gg1.w};
        float on[8];
#pragma unroll
        for (int j = 0; j < 8; j++) {
            float gvv = gr[j];
            float sw  = gvv / (1.f + __expf(-gvv));
            on[j] = o[i][j] * rms * wr[j] * sw;
        }
        *(float4*)(g_on + r + v0)     = make_float4(on[0],on[1],on[2],on[3]);
        *(float4*)(g_on + r + v0 + 4) = make_float4(on[4],on[5],on[6],on[7]);
    }
}

// ---------------------------------------------------------------------------
extern "C" void kernel_launch(void* const* d_in, const int* in_sizes, int n_in,
                              void* d_out, int out_size)
{
    const float* x        = (const float*)d_in[0];
    const float* Wq       = (const float*)d_in[1];
    const float* Wk       = (const float*)d_in[2];
    const float* Wv       = (const float*)d_in[3];
    const float* Wg       = (const float*)d_in[4];
    const float* Wgk1     = (const float*)d_in[5];
    const float* Wgk2     = (const float*)d_in[6];
    const float* bgk2     = (const float*)d_in[7];
    const float* g_norm_w = (const float*)d_in[8];
    const float* Wo       = (const float*)d_in[9];
    float* out = (float*)d_out;

    dim3 gp(16, 8, 4);
    proj4_kernel<<<gp, 256>>>(x, Wq, Wk, Wv, Wg);
    lowrank1_kernel<<<64, 256>>>(x, Wgk1);
    gk_kernel<<<4096, 256>>>(Wgk2, bgk2);
    prep_kernel<<<128, 128>>>();
    chunk_kv_kernel<<<128, 256>>>();
    state_scan_kernel<<<16, 256>>>();
    chunk_out_kernel<<<128, 256>>>(g_norm_w);
    dim3 go(16, 8, 1);
    out_gemm_kernel<<<go, 256>>>(Wo, out);
}

// round 5
// speedup vs baseline: 3.2155x; 1.7663x over previous
#include <cuda_runtime.h>
#include <cuda_bf16.h>
#include <math.h>
#include <cstdint>

// Shapes (fixed)
#define DIMN   1024
#define BB     2
#define TT     512
#define HH     8
#define HKD    128
#define NROWS  (BB*TT)          // 1024
#define CH     64               // chunk length
#define NC     (TT/CH)          // 8 chunks
#define QSCALE 0.08838834764831845f   // 128^-0.5
#define GNORM  0.0625f                // 1/16

// ---------------------------------------------------------------------------
// Scratch (no cudaMalloc allowed)
// ---------------------------------------------------------------------------
__device__ float g_q [NROWS*DIMN];
__device__ float g_k [NROWS*DIMN];
__device__ float g_v [NROWS*DIMN];
__device__ float g_g [NROWS*DIMN];
__device__ float g_gk[NROWS*DIMN];
__device__ float g_t1[NROWS*16];
__device__ float g_on[NROWS*DIMN];
// chunked-GLA scratch
__device__ float g_qg[NROWS*DIMN];
__device__ float g_kd[NROWS*DIMN];
__device__ float g_kr[NROWS*DIMN];
__device__ float g_kv[16*NC*HKD*HKD];
__device__ float g_S [16*NC*HKD*HKD];
__device__ float g_dc[16*NC*HKD];
// bf16 split-precision operands
__device__ __nv_bfloat16 g_xhi [NROWS*DIMN];
__device__ __nv_bfloat16 g_xlo [NROWS*DIMN];
__device__ __nv_bfloat16 g_onhi[NROWS*DIMN];
__device__ __nv_bfloat16 g_onlo[NROWS*DIMN];
__device__ __nv_bfloat16 g_Whi [5*DIMN*DIMN];   // transposed: [n][k]
__device__ __nv_bfloat16 g_Wlo [5*DIMN*DIMN];

// ---------------------------------------------------------------------------
// PTX helpers (all non-'a'-gated: cp.async / ldmatrix / mma.sync)
// ---------------------------------------------------------------------------
__device__ __forceinline__ uint32_t smem_u32(const void* p) {
    uint32_t a;
    asm("{ .reg .u64 t; cvta.to.shared.u64 t, %1; cvt.u32.u64 %0, t; }"
        : "=r"(a) : "l"(p));
    return a;
}
__device__ __forceinline__ void cp16(uint32_t dst, const void* src) {
    asm volatile("cp.async.cg.shared.global [%0], [%1], 16;"
                 :: "r"(dst), "l"(src) : "memory");
}
__device__ __forceinline__ void cp_commit() {
    asm volatile("cp.async.commit_group;" ::: "memory");
}
__device__ __forceinline__ void ldsm4(uint32_t& r0, uint32_t& r1,
                                      uint32_t& r2, uint32_t& r3, uint32_t a) {
    asm volatile("ldmatrix.sync.aligned.m8n8.x4.shared.b16 {%0,%1,%2,%3}, [%4];"
                 : "=r"(r0), "=r"(r1), "=r"(r2), "=r"(r3) : "r"(a));
}
__device__ __forceinline__ void mma16816(float* c, const uint32_t* a,
                                         const uint32_t* b) {
    asm volatile("mma.sync.aligned.m16n8k16.row.col.f32.bf16.bf16.f32 "
        "{%0,%1,%2,%3}, {%4,%5,%6,%7}, {%8,%9}, {%0,%1,%2,%3};"
        : "+f"(c[0]), "+f"(c[1]), "+f"(c[2]), "+f"(c[3])
        : "r"(a[0]), "r"(a[1]), "r"(a[2]), "r"(a[3]), "r"(b[0]), "r"(b[1]));
}

// ---------------------------------------------------------------------------
// bf16 split conversions
// ---------------------------------------------------------------------------
__device__ __forceinline__ void split_bf16(float x, __nv_bfloat16& h, __nv_bfloat16& l) {
    h = __float2bfloat16(x);
    l = __float2bfloat16(x - __bfloat162float(h));
}

__device__ __forceinline__ void conv_act_body(
    const float* __restrict__ src, __nv_bfloat16* __restrict__ dhi,
    __nv_bfloat16* __restrict__ dlo)
{
    int i = blockIdx.x * 256 + threadIdx.x;       // float4 index
    float4 v = ((const float4*)src)[i];
    __nv_bfloat16 h[4], l[4];
    split_bf16(v.x, h[0], l[0]); split_bf16(v.y, h[1], l[1]);
    split_bf16(v.z, h[2], l[2]); split_bf16(v.w, h[3], l[3]);
    __nv_bfloat162* ph = (__nv_bfloat162*)dhi;
    __nv_bfloat162* pl = (__nv_bfloat162*)dlo;
    ph[i*2]   = __nv_bfloat162(h[0], h[1]);
    ph[i*2+1] = __nv_bfloat162(h[2], h[3]);
    pl[i*2]   = __nv_bfloat162(l[0], l[1]);
    pl[i*2+1] = __nv_bfloat162(l[2], l[3]);
}

// NOTE: device globals are referenced INSIDE the kernels (passing them as
// kernel arguments from host code passes the host shadow symbol -> silent
// wrong-memory writes under ATS).
__global__ __launch_bounds__(256) void conv_x_kernel(const float* __restrict__ x)
{
    conv_act_body(x, g_xhi, g_xlo);
}
__global__ __launch_bounds__(256) void conv_on_kernel()
{
    conv_act_body(g_on, g_onhi, g_onlo);
}

// W fp32 [k][n] -> transposed bf16 hi/lo [n][k] (5 weights via z)
__global__ __launch_bounds__(256) void conv_w_kernel(
    const float* __restrict__ Wq, const float* __restrict__ Wk,
    const float* __restrict__ Wv, const float* __restrict__ Wg,
    const float* __restrict__ Wo)
{
    const float* Ws[5] = {Wq, Wk, Wv, Wg, Wo};
    const float* W = Ws[blockIdx.z];
    __nv_bfloat16* Dhi = g_Whi + (size_t)blockIdx.z * DIMN * DIMN;
    __nv_bfloat16* Dlo = g_Wlo + (size_t)blockIdx.z * DIMN * DIMN;

    __shared__ float s[32][33];
    int tx = threadIdx.x & 31, ty = threadIdx.x >> 5;   // 32 x 8
    int kt = blockIdx.y * 32, nt = blockIdx.x * 32;
#pragma unroll
    for (int j = 0; j < 4; j++)
        s[ty + j*8][tx] = W[(kt + ty + j*8) * DIMN + nt + tx];
    __syncthreads();
#pragma unroll
    for (int j = 0; j < 4; j++) {
        int n = nt + ty + j*8, k = kt + tx;
        float w = s[tx][ty + j*8];
        __nv_bfloat16 h, l; split_bf16(w, h, l);
        Dhi[(size_t)n * DIMN + k] = h;
        Dlo[(size_t)n * DIMN + k] = l;
    }
}

// ---------------------------------------------------------------------------
// HMMA split-3 GEMM: C[1024,1024] = alpha * A @ W
//   Ahi/Alo row-major [m][k]; Bhi/Blo = W^T row-major [n][k].
//   BM=128, BN=64, BK=32, 8 warps, warp tile 32x32, double-buffered cp.async.
//   Smem rows are 32 bf16 (64B = 4 x 16B chunks); swizzle: chunk ^= (row>>1)&3.
// ---------------------------------------------------------------------------
#define STG_BYTES 24576
#define OFF_AHI 0
#define OFF_ALO 8192
#define OFF_BHI 16384
#define OFF_BLO 20480
#define SMEM_GEMM (2*STG_BYTES)     // 48 KB exactly (no opt-in needed)

__device__ __forceinline__ uint32_t sw_addr(uint32_t region, int row, int chunk) {
    return region + row * 64 + ((chunk ^ ((row >> 1) & 3)) << 4);
}

__device__ __forceinline__ void load_stage(
    uint32_t sb, int s,
    const __nv_bfloat16* __restrict__ Ahi, const __nv_bfloat16* __restrict__ Alo,
    const __nv_bfloat16* __restrict__ Bhi, const __nv_bfloat16* __restrict__ Blo,
    int m0, int n0, int k0, int tid)
{
    uint32_t st = sb + s * STG_BYTES;
#pragma unroll
    for (int i = 0; i < 2; i++) {
        int idx = tid + (i << 8);          // 0..511
        int row = idx >> 2, c = idx & 3;
        const size_t go = (size_t)(m0 + row) * DIMN + k0 + c * 8;
        cp16(sw_addr(st + OFF_AHI, row, c), Ahi + go);
        cp16(sw_addr(st + OFF_ALO, row, c), Alo + go);
    }
    {
        int row = tid >> 2, c = tid & 3;   // 64 rows x 4 chunks
        const size_t go = (size_t)(n0 + row) * DIMN + k0 + c * 8;
        cp16(sw_addr(st + OFF_BHI, row, c), Bhi + go);
        cp16(sw_addr(st + OFF_BLO, row, c), Blo + go);
    }
    cp_commit();
}

__device__ __forceinline__ void gemm_body(
    const __nv_bfloat16* __restrict__ Ahi, const __nv_bfloat16* __restrict__ Alo,
    const __nv_bfloat16* __restrict__ Bhi, const __nv_bfloat16* __restrict__ Blo,
    float* __restrict__ C, float alpha, char* smem)
{
    const int tid  = threadIdx.x;
    const int wid  = tid >> 5;
    const int lane = tid & 31;
    const int m0 = blockIdx.y * 128;
    const int n0 = blockIdx.x * 64;
    const int wm0 = (wid & 3) * 32;     // warp m within block
    const int wn0 = (wid >> 2) * 32;    // warp n within block
    const uint32_t sb = smem_u32(smem);

    float acc[2][4][4];
#pragma unroll
    for (int mt = 0; mt < 2; mt++)
#pragma unroll
        for (int nt = 0; nt < 4; nt++)
#pragma unroll
            for (int i = 0; i < 4; i++) acc[mt][nt][i] = 0.f;

    load_stage(sb, 0, Ahi, Alo, Bhi, Blo, m0, n0, 0, tid);

    const int lr = lane & 15;
    const int lc = lane >> 4;

    for (int kt = 0; kt < 32; kt++) {
        if (kt < 31) {
            load_stage(sb, (kt + 1) & 1, Ahi, Alo, Bhi, Blo, m0, n0,
                       (kt + 1) * 32, tid);
            asm volatile("cp.async.wait_group 1;" ::: "memory");
        } else {
            asm volatile("cp.async.wait_group 0;" ::: "memory");
        }
        __syncthreads();

        const uint32_t st = sb + (kt & 1) * STG_BYTES;
#pragma unroll
        for (int ks = 0; ks < 2; ks++) {
            const int ch = ks * 2 + lc;
            uint32_t ahi[2][4], alo[2][4];
#pragma unroll
            for (int mt = 0; mt < 2; mt++) {
                int row = wm0 + mt * 16 + lr;
                ldsm4(ahi[mt][0], ahi[mt][1], ahi[mt][2], ahi[mt][3],
                      sw_addr(st + OFF_AHI, row, ch));
                ldsm4(alo[mt][0], alo[mt][1], alo[mt][2], alo[mt][3],
                      sw_addr(st + OFF_ALO, row, ch));
            }
            uint32_t bhi[4][2], blo[4][2];
#pragma unroll
            for (int ng = 0; ng < 2; ng++) {
                int row = wn0 + ng * 16 + lr;
                uint32_t t0, t1, t2, t3;
                ldsm4(t0, t1, t2, t3, sw_addr(st + OFF_BHI, row, ch));
                bhi[ng*2][0] = t0; bhi[ng*2+1][0] = t1;
                bhi[ng*2][1] = t2; bhi[ng*2+1][1] = t3;
                ldsm4(t0, t1, t2, t3, sw_addr(st + OFF_BLO, row, ch));
                blo[ng*2][0] = t0; blo[ng*2+1][0] = t1;
                blo[ng*2][1] = t2; blo[ng*2+1][1] = t3;
            }
#pragma unroll
            for (int mt = 0; mt < 2; mt++)
#pragma unroll
                for (int nt = 0; nt < 4; nt++) {
                    mma16816(acc[mt][nt], ahi[mt], bhi[nt]);
                    mma16816(acc[mt][nt], ahi[mt], blo[nt]);
                    mma16816(acc[mt][nt], alo[mt], bhi[nt]);
                }
        }
        __syncthreads();
    }

    // Epilogue: c0,c1 -> (m = l/4, n = 2(l%4)); c2,c3 -> (m = l/4 + 8)
    const int er = lane >> 2;
    const int ec = (lane & 3) << 1;
#pragma unroll
    for (int mt = 0; mt < 2; mt++)
#pragma unroll
        for (int nt = 0; nt < 4; nt++) {
            int row = m0 + wm0 + mt * 16 + er;
            int col = n0 + wn0 + nt * 8 + ec;
            float2 v0 = make_float2(acc[mt][nt][0] * alpha, acc[mt][nt][1] * alpha);
            float2 v1 = make_float2(acc[mt][nt][2] * alpha, acc[mt][nt][3] * alpha);
            *(float2*)(C + (size_t)row * DIMN + col)       = v0;
            *(float2*)(C + (size_t)(row + 8) * DIMN + col) = v1;
        }
}

__global__ __launch_bounds__(256) void gemm4_kernel()
{
    extern __shared__ char smem[];
    const int z = blockIdx.z;
    const __nv_bfloat16* Bhi = g_Whi + (size_t)z * DIMN * DIMN;
    const __nv_bfloat16* Blo = g_Wlo + (size_t)z * DIMN * DIMN;
    float* outs[4] = {g_q, g_k, g_v, g_g};
    float alpha = (z == 0) ? QSCALE : 1.f;
    gemm_body(g_xhi, g_xlo, Bhi, Blo, outs[z], alpha, smem);
}

__global__ __launch_bounds__(256) void gemmo_kernel(float* __restrict__ out)
{
    extern __shared__ char smem[];
    gemm_body(g_onhi, g_onlo, g_Whi + (size_t)4 * DIMN * DIMN,
              g_Wlo + (size_t)4 * DIMN * DIMN, out, 1.f, smem);
}

// ---------------------------------------------------------------------------
// Low-rank gate path
// ---------------------------------------------------------------------------
__global__ __launch_bounds__(256) void lowrank1_kernel(
    const float* __restrict__ x, const float* __restrict__ Wgk1)
{
    int r   = threadIdx.x >> 4;
    int c   = threadIdx.x & 15;
    int row = blockIdx.x * 16 + r;
    const float* xr = x + row * 1024;
    float acc = 0.f;
#pragma unroll 8
    for (int k = 0; k < 1024; k++)
        acc = fmaf(xr[k], Wgk1[k * 16 + c], acc);
    g_t1[row * 16 + c] = acc;
}

__global__ __launch_bounds__(256) void gk_kernel(
    const float* __restrict__ Wgk2, const float* __restrict__ bgk2)
{
    __shared__ float sT[16];
    int m = blockIdx.x >> 2;
    int n = ((blockIdx.x & 3) << 8) + threadIdx.x;
    if (threadIdx.x < 16) sT[threadIdx.x] = g_t1[m * 16 + threadIdx.x];
    __syncthreads();
    float acc = bgk2[n];
#pragma unroll
    for (int j = 0; j < 16; j++)
        acc = fmaf(sT[j], Wgk2[j * 1024 + n], acc);
    float ls = fminf(acc, 0.f) - log1pf(__expf(-fabsf(acc)));
    g_gk[m * 1024 + n] = ls * GNORM;
}

// ---------------------------------------------------------------------------
// Chunked GLA
// ---------------------------------------------------------------------------
__device__ __forceinline__ int row_off(int b, int h, int t)
{
    return (((b * TT + t) * HH + h) << 7);
}

// prep: 512 threads = 128 ch x 4 t-segments of 16; smem prefix across segments
__global__ __launch_bounds__(512) void prep_kernel()
{
    const int bhc = blockIdx.x;
    const int bh  = bhc >> 3, c0 = bhc & 7;
    const int b   = bh >> 3,  h  = bh & 7;
    const int ch  = threadIdx.x & 127;
    const int tg  = threadIdx.x >> 7;          // 0..3
    const int tbase = c0 * CH + tg * 16;

    __shared__ float gsum[4][128];

    float loc[16];
    float acc = 0.f;
#pragma unroll
    for (int s = 0; s < 16; s++) {
        loc[s] = g_gk[row_off(b, h, tbase + s) + ch];
        acc += loc[s];
    }
    gsum[tg][ch] = acc;
    __syncthreads();

    float off = 0.f;
#pragma unroll
    for (int g = 0; g < 4; g++)
        if (g < tg) off += gsum[g][ch];
    float tot = gsum[0][ch] + gsum[1][ch] + gsum[2][ch] + gsum[3][ch];

    float bacc = off;
#pragma unroll 4
    for (int s = 0; s < 16; s++) {
        bacc += loc[s];
        int r = row_off(b, h, tbase + s) + ch;
        float q = g_q[r], k = g_k[r];
        g_qg[r] = q * __expf(bacc);
        g_kd[r] = k * __expf(-bacc);
        g_kr[r] = k * __expf(tot - bacc);
    }
    if (threadIdx.x < 128)
        g_dc[bhc * 128 + ch] = __expf(tot);
}

// chunk_kv: KV_c[128][128] = sum_s k~_s^T v_s
__global__ __launch_bounds__(256) void chunk_kv_kernel()
{
    const int bhc = blockIdx.x;
    const int bh  = bhc >> 3, c0 = bhc & 7;
    const int b   = bh >> 3,  h  = bh & 7;
    const int tid = threadIdx.x;
    const int tr  = tid >> 4, tc = tid & 15;
    const int kr0 = tr << 3, vc0 = tc << 3;
    const int tbase = c0 * CH;

    __shared__ float sK[16][128];
    __shared__ float sV[16][128];

    float acc[8][8];
#pragma unroll
    for (int i = 0; i < 8; i++)
#pragma unroll
        for (int j = 0; j < 8; j++) acc[i][j] = 0.f;

    for (int st = 0; st < 4; st++) {
#pragma unroll
        for (int u = 0; u < 2; u++) {
            int f  = tid + (u << 8);
            int sr = f >> 5;
            int sc = (f & 31) << 2;
            int r  = row_off(b, h, tbase + st * 16 + sr) + sc;
            *(float4*)&sK[sr][sc] = *(const float4*)(g_kr + r);
            *(float4*)&sV[sr][sc] = *(const float4*)(g_v + r);
        }
        __syncthreads();
#pragma unroll
        for (int ss = 0; ss < 16; ss++) {
            float4 k0 = *(const float4*)&sK[ss][kr0];
            float4 k1 = *(const float4*)&sK[ss][kr0 + 4];
            float4 v0 = *(const float4*)&sV[ss][vc0];
            float4 v1 = *(const float4*)&sV[ss][vc0 + 4];
            float kr[8] = {k0.x,k0.y,k0.z,k0.w,k1.x,k1.y,k1.z,k1.w};
            float vr[8] = {v0.x,v0.y,v0.z,v0.w,v1.x,v1.y,v1.z,v1.w};
#pragma unroll
            for (int i = 0; i < 8; i++)
#pragma unroll
                for (int j = 0; j < 8; j++)
                    acc[i][j] = fmaf(kr[i], vr[j], acc[i][j]);
        }
        __syncthreads();
    }

    float* dst = g_kv + (size_t)bhc * 16384;
#pragma unroll
    for (int i = 0; i < 8; i++) {
        *(float4*)(dst + (kr0 + i) * 128 + vc0)     = make_float4(acc[i][0],acc[i][1],acc[i][2],acc[i][3]);
        *(float4*)(dst + (kr0 + i) * 128 + vc0 + 4) = make_float4(acc[i][4],acc[i][5],acc[i][6],acc[i][7]);
    }
}

// state scan: parallel over (bh, v-group of 16); serial over 8 chunks.
__global__ __launch_bounds__(256) void state_scan_kernel()
{
    const int bh = blockIdx.x >> 3;
    const int vg = blockIdx.x & 7;
    const int tid = threadIdx.x;
    const int k    = tid >> 1;
    const int voff = vg * 16 + (tid & 1) * 8;

    float4 S0 = make_float4(0.f,0.f,0.f,0.f);
    float4 S1 = make_float4(0.f,0.f,0.f,0.f);

    for (int c = 0; c < NC; c++) {
        const int bhc = bh * NC + c;
        const size_t base = (size_t)bhc * 16384 + (size_t)k * 128 + voff;
        const float d = g_dc[bhc * 128 + k];
        *(float4*)(g_S + base)     = S0;
        *(float4*)(g_S + base + 4) = S1;
        float4 a = *(const float4*)(g_kv + base);
        float4 b = *(const float4*)(g_kv + base + 4);
        S0.x = fmaf(S0.x, d, a.x); S0.y = fmaf(S0.y, d, a.y);
        S0.z = fmaf(S0.z, d, a.z); S0.w = fmaf(S0.w, d, a.w);
        S1.x = fmaf(S1.x, d, b.x); S1.y = fmaf(S1.y, d, b.y);
        S1.z = fmaf(S1.z, d, b.z); S1.w = fmaf(S1.w, d, b.w);
    }
}

// chunk_out: o = q~ @ S_c + tril(q~ @ k^^T) @ V, fused gated RMSNorm -> g_on
__global__ __launch_bounds__(256) void chunk_out_kernel(
    const float* __restrict__ g_norm_w)
{
    const int bhc = blockIdx.x;
    const int bh  = bhc >> 3, c0 = bhc & 7;
    const int b   = bh >> 3,  h  = bh & 7;
    const int tid = threadIdx.x;
    const int tr  = tid >> 4, tc = tid & 15;
    const int t0  = tr << 2;
    const int v0  = tc << 3;
    const int tbase = c0 * CH;

    __shared__ float sQ [16][68];
    __shared__ float sKd[16][68];
    __shared__ float sS [16][128];
    __shared__ float sA [64][68];
    __shared__ float sV [16][128];

    float o[4][8];
    float a2[4][4];
#pragma unroll
    for (int i = 0; i < 4; i++) {
#pragma unroll
        for (int j = 0; j < 8; j++) o[i][j] = 0.f;
#pragma unroll
        for (int j = 0; j < 4; j++) a2[i][j] = 0.f;
    }

    const size_t Sbase = (size_t)bhc * 16384;

    for (int k0 = 0; k0 < 128; k0 += 16) {
        {
            int tt = tid >> 2;
            int c4 = (tid & 3) << 2;
            int r  = row_off(b, h, tbase + tt) + k0 + c4;
            float4 qv = *(const float4*)(g_qg + r);
            sQ[c4+0][tt] = qv.x; sQ[c4+1][tt] = qv.y;
            sQ[c4+2][tt] = qv.z; sQ[c4+3][tt] = qv.w;
            float4 kv = *(const float4*)(g_kd + r);
            sKd[c4+0][tt] = kv.x; sKd[c4+1][tt] = kv.y;
            sKd[c4+2][tt] = kv.z; sKd[c4+3][tt] = kv.w;
        }
#pragma unroll
        for (int u = 0; u < 2; u++) {
            int f  = tid + (u << 8);
            int sr = f >> 5;
            int sc = (f & 31) << 2;
            *(float4*)&sS[sr][sc] =
                *(const float4*)(g_S + Sbase + (k0 + sr) * 128 + sc);
        }
        __syncthreads();

#pragma unroll
        for (int kk = 0; kk < 16; kk++) {
            float4 q4  = *(const float4*)&sQ[kk][t0];
            float4 s0  = *(const float4*)&sS[kk][v0];
            float4 s1  = *(const float4*)&sS[kk][v0 + 4];
            float4 kd4 = *(const float4*)&sKd[kk][tc << 2];
            float qr[4] = {q4.x, q4.y, q4.z, q4.w};
            float sr_[8] = {s0.x,s0.y,s0.z,s0.w,s1.x,s1.y,s1.z,s1.w};
            float kr[4] = {kd4.x,kd4.y,kd4.z,kd4.w};
#pragma unroll
            for (int i = 0; i < 4; i++) {
#pragma unroll
                for (int j = 0; j < 8; j++)
                    o[i][j] = fmaf(qr[i], sr_[j], o[i][j]);
#pragma unroll
                for (int j = 0; j < 4; j++)
                    a2[i][j] = fmaf(qr[i], kr[j], a2[i][j]);
            }
        }
        __syncthreads();
    }

#pragma unroll
    for (int i = 0; i < 4; i++) {
        int t = t0 + i;
#pragma unroll
        for (int j = 0; j < 4; j++) {
            int s = (tc << 2) + j;
            sA[t][s] = (s <= t) ? a2[i][j] : 0.f;
        }
    }
    __syncthreads();

    for (int st = 0; st < 4; st++) {
#pragma unroll
        for (int u = 0; u < 2; u++) {
            int f  = tid + (u << 8);
            int sr = f >> 5;
            int sc = (f & 31) << 2;
            int r  = row_off(b, h, tbase + st * 16 + sr) + sc;
            *(float4*)&sV[sr][sc] = *(const float4*)(g_v + r);
        }
        __syncthreads();
#pragma unroll
        for (int ss = 0; ss < 16; ss++) {
            int s = st * 16 + ss;
            float a[4];
#pragma unroll
            for (int i = 0; i < 4; i++) a[i] = sA[t0 + i][s];
            float4 vv0 = *(const float4*)&sV[ss][v0];
            float4 vv1 = *(const float4*)&sV[ss][v0 + 4];
            float vr[8] = {vv0.x,vv0.y,vv0.z,vv0.w,vv1.x,vv1.y,vv1.z,vv1.w};
#pragma unroll
            for (int i = 0; i < 4; i++)
#pragma unroll
                for (int j = 0; j < 8; j++)
                    o[i][j] = fmaf(a[i], vr[j], o[i][j]);
        }
        __syncthreads();
    }

    float4 w0 = *(const float4*)(g_norm_w + v0);
    float4 w1 = *(const float4*)(g_norm_w + v0 + 4);
    float wr[8] = {w0.x,w0.y,w0.z,w0.w,w1.x,w1.y,w1.z,w1.w};

#pragma unroll
    for (int i = 0; i < 4; i++) {
        float ss = 0.f;
#pragma unroll
        for (int j = 0; j < 8; j++) ss = fmaf(o[i][j], o[i][j], ss);
#pragma unroll
        for (int off = 1; off < 16; off <<= 1)
            ss += __shfl_xor_sync(0xffffffffu, ss, off);
        float rms = rsqrtf(ss * (1.f / 128.f) + 1e-5f);

        int r = row_off(b, h, tbase + t0 + i);
        float4 gg0 = *(const float4*)(g_g + r + v0);
        float4 gg1 = *(const float4*)(g_g + r + v0 + 4);
        float gr[8] = {gg0.x,gg0.y,gg0.z,gg0.w,gg1.x,gg1.y,gg1.z,gg1.w};
        float on[8];
#pragma unroll
        for (int j = 0; j < 8; j++) {
            float gvv = gr[j];
            float sw  = gvv / (1.f + __expf(-gvv));
            on[j] = o[i][j] * rms * wr[j] * sw;
        }
        *(float4*)(g_on + r + v0)     = make_float4(on[0],on[1],on[2],on[3]);
        *(float4*)(g_on + r + v0 + 4) = make_float4(on[4],on[5],on[6],on[7]);
    }
}

// ---------------------------------------------------------------------------
extern "C" void kernel_launch(void* const* d_in, const int* in_sizes, int n_in,
                              void* d_out, int out_size)
{
    const float* x        = (const float*)d_in[0];
    const float* Wq       = (const float*)d_in[1];
    const float* Wk       = (const float*)d_in[2];
    const float* Wv       = (const float*)d_in[3];
    const float* Wg       = (const float*)d_in[4];
    const float* Wgk1     = (const float*)d_in[5];
    const float* Wgk2     = (const float*)d_in[6];
    const float* bgk2     = (const float*)d_in[7];
    const float* g_norm_w = (const float*)d_in[8];
    const float* Wo       = (const float*)d_in[9];
    float* out = (float*)d_out;

    conv_w_kernel<<<dim3(32, 32, 5), dim3(256)>>>(Wq, Wk, Wv, Wg, Wo);
    conv_x_kernel<<<1024, 256>>>(x);
    gemm4_kernel<<<dim3(16, 8, 4), 256, SMEM_GEMM>>>();
    lowrank1_kernel<<<64, 256>>>(x, Wgk1);
    gk_kernel<<<4096, 256>>>(Wgk2, bgk2);
    prep_kernel<<<128, 512>>>();
    chunk_kv_kernel<<<128, 256>>>();
    state_scan_kernel<<<128, 256>>>();
    chunk_out_kernel<<<128, 256>>>(g_norm_w);
    conv_on_kernel<<<1024, 256>>>();
    gemmo_kernel<<<dim3(16, 8), 256, SMEM_GEMM>>>(out);
}

// round 6
// speedup vs baseline: 3.8405x; 1.1944x over previous
#include <cuda_runtime.h>
#include <cuda_bf16.h>
#include <math.h>
#include <cstdint>

// Shapes (fixed)
#define DIMN   1024
#define BB     2
#define TT     512
#define HH     8
#define HKD    128
#define NROWS  (BB*TT)          // 1024
#define CH     64               // chunk length
#define NC     (TT/CH)          // 8 chunks
#define QSCALE 0.08838834764831845f   // 128^-0.5
#define GNORM  0.0625f                // 1/16

// ---------------------------------------------------------------------------
// Scratch (no cudaMalloc allowed)
// ---------------------------------------------------------------------------
__device__ float g_q [NROWS*DIMN];
__device__ float g_k [NROWS*DIMN];
__device__ float g_v [NROWS*DIMN];
__device__ float g_g [NROWS*DIMN];
__device__ float g_gk[NROWS*DIMN];
__device__ float g_on[NROWS*DIMN];
// chunked-GLA scratch
__device__ float g_qg[NROWS*DIMN];
__device__ float g_kd[NROWS*DIMN];
__device__ float g_kr[NROWS*DIMN];
__device__ float g_kv[16*NC*HKD*HKD];
__device__ float g_S [16*NC*HKD*HKD];
__device__ float g_dc[16*NC*HKD];
// bf16 split-precision operands
__device__ __nv_bfloat16 g_xhi [NROWS*DIMN];
__device__ __nv_bfloat16 g_xlo [NROWS*DIMN];
__device__ __nv_bfloat16 g_onhi[NROWS*DIMN];
__device__ __nv_bfloat16 g_onlo[NROWS*DIMN];
__device__ __nv_bfloat16 g_Whi [5*DIMN*DIMN];   // transposed: [n][k]
__device__ __nv_bfloat16 g_Wlo [5*DIMN*DIMN];

// ---------------------------------------------------------------------------
// PTX helpers (all non-'a'-gated: cp.async / ldmatrix / mma.sync)
// ---------------------------------------------------------------------------
__device__ __forceinline__ uint32_t smem_u32(const void* p) {
    uint32_t a;
    asm("{ .reg .u64 t; cvta.to.shared.u64 t, %1; cvt.u32.u64 %0, t; }"
        : "=r"(a) : "l"(p));
    return a;
}
__device__ __forceinline__ void cp16(uint32_t dst, const void* src) {
    asm volatile("cp.async.cg.shared.global [%0], [%1], 16;"
                 :: "r"(dst), "l"(src) : "memory");
}
__device__ __forceinline__ void cp_commit() {
    asm volatile("cp.async.commit_group;" ::: "memory");
}
__device__ __forceinline__ void ldsm4(uint32_t& r0, uint32_t& r1,
                                      uint32_t& r2, uint32_t& r3, uint32_t a) {
    asm volatile("ldmatrix.sync.aligned.m8n8.x4.shared.b16 {%0,%1,%2,%3}, [%4];"
                 : "=r"(r0), "=r"(r1), "=r"(r2), "=r"(r3) : "r"(a));
}
__device__ __forceinline__ void mma16816(float* c, const uint32_t* a,
                                         const uint32_t* b) {
    asm volatile("mma.sync.aligned.m16n8k16.row.col.f32.bf16.bf16.f32 "
        "{%0,%1,%2,%3}, {%4,%5,%6,%7}, {%8,%9}, {%0,%1,%2,%3};"
        : "+f"(c[0]), "+f"(c[1]), "+f"(c[2]), "+f"(c[3])
        : "r"(a[0]), "r"(a[1]), "r"(a[2]), "r"(a[3]), "r"(b[0]), "r"(b[1]));
}

// ---------------------------------------------------------------------------
// bf16 split conversions
// ---------------------------------------------------------------------------
__device__ __forceinline__ void split_bf16(float x, __nv_bfloat16& h, __nv_bfloat16& l) {
    h = __float2bfloat16(x);
    l = __float2bfloat16(x - __bfloat162float(h));
}

__device__ __forceinline__ void conv_act_body(
    const float* __restrict__ src, __nv_bfloat16* __restrict__ dhi,
    __nv_bfloat16* __restrict__ dlo)
{
    int i = blockIdx.x * 256 + threadIdx.x;       // float4 index
    float4 v = ((const float4*)src)[i];
    __nv_bfloat16 h[4], l[4];
    split_bf16(v.x, h[0], l[0]); split_bf16(v.y, h[1], l[1]);
    split_bf16(v.z, h[2], l[2]); split_bf16(v.w, h[3], l[3]);
    __nv_bfloat162* ph = (__nv_bfloat162*)dhi;
    __nv_bfloat162* pl = (__nv_bfloat162*)dlo;
    ph[i*2]   = __nv_bfloat162(h[0], h[1]);
    ph[i*2+1] = __nv_bfloat162(h[2], h[3]);
    pl[i*2]   = __nv_bfloat162(l[0], l[1]);
    pl[i*2+1] = __nv_bfloat162(l[2], l[3]);
}

// NOTE: device globals are referenced INSIDE the kernels (passing them as
// kernel arguments from host code passes the host shadow symbol -> silent
// wrong-memory writes under ATS).
__global__ __launch_bounds__(256) void conv_x_kernel(const float* __restrict__ x)
{
    conv_act_body(x, g_xhi, g_xlo);
}
__global__ __launch_bounds__(256) void conv_on_kernel()
{
    conv_act_body(g_on, g_onhi, g_onlo);
}

// W fp32 [k][n] -> transposed bf16 hi/lo [n][k] (5 weights via z)
__global__ __launch_bounds__(256) void conv_w_kernel(
    const float* __restrict__ Wq, const float* __restrict__ Wk,
    const float* __restrict__ Wv, const float* __restrict__ Wg,
    const float* __restrict__ Wo)
{
    const float* Ws[5] = {Wq, Wk, Wv, Wg, Wo};
    const float* W = Ws[blockIdx.z];
    __nv_bfloat16* Dhi = g_Whi + (size_t)blockIdx.z * DIMN * DIMN;
    __nv_bfloat16* Dlo = g_Wlo + (size_t)blockIdx.z * DIMN * DIMN;

    __shared__ float s[32][33];
    int tx = threadIdx.x & 31, ty = threadIdx.x >> 5;   // 32 x 8
    int kt = blockIdx.y * 32, nt = blockIdx.x * 32;
#pragma unroll
    for (int j = 0; j < 4; j++)
        s[ty + j*8][tx] = W[(kt + ty + j*8) * DIMN + nt + tx];
    __syncthreads();
#pragma unroll
    for (int j = 0; j < 4; j++) {
        int n = nt + ty + j*8, k = kt + tx;
        float w = s[tx][ty + j*8];
        __nv_bfloat16 h, l; split_bf16(w, h, l);
        Dhi[(size_t)n * DIMN + k] = h;
        Dlo[(size_t)n * DIMN + k] = l;
    }
}

// ---------------------------------------------------------------------------
// HMMA split-3 GEMM: C[1024,1024] = alpha * A @ W
//   Ahi/Alo row-major [m][k]; Bhi/Blo = W^T row-major [n][k].
//   BM=128, BN=64, BK=32, 8 warps, warp tile 32x32, double-buffered cp.async.
//   Smem rows are 32 bf16 (64B = 4 x 16B chunks); swizzle: chunk ^= (row>>1)&3.
// ---------------------------------------------------------------------------
#define STG_BYTES 24576
#define OFF_AHI 0
#define OFF_ALO 8192
#define OFF_BHI 16384
#define OFF_BLO 20480
#define SMEM_GEMM (2*STG_BYTES)     // 48 KB exactly (no opt-in needed)

__device__ __forceinline__ uint32_t sw_addr(uint32_t region, int row, int chunk) {
    return region + row * 64 + ((chunk ^ ((row >> 1) & 3)) << 4);
}

__device__ __forceinline__ void load_stage(
    uint32_t sb, int s,
    const __nv_bfloat16* __restrict__ Ahi, const __nv_bfloat16* __restrict__ Alo,
    const __nv_bfloat16* __restrict__ Bhi, const __nv_bfloat16* __restrict__ Blo,
    int m0, int n0, int k0, int tid)
{
    uint32_t st = sb + s * STG_BYTES;
#pragma unroll
    for (int i = 0; i < 2; i++) {
        int idx = tid + (i << 8);          // 0..511
        int row = idx >> 2, c = idx & 3;
        const size_t go = (size_t)(m0 + row) * DIMN + k0 + c * 8;
        cp16(sw_addr(st + OFF_AHI, row, c), Ahi + go);
        cp16(sw_addr(st + OFF_ALO, row, c), Alo + go);
    }
    {
        int row = tid >> 2, c = tid & 3;   // 64 rows x 4 chunks
        const size_t go = (size_t)(n0 + row) * DIMN + k0 + c * 8;
        cp16(sw_addr(st + OFF_BHI, row, c), Bhi + go);
        cp16(sw_addr(st + OFF_BLO, row, c), Blo + go);
    }
    cp_commit();
}

__device__ __forceinline__ void gemm_body(
    const __nv_bfloat16* __restrict__ Ahi, const __nv_bfloat16* __restrict__ Alo,
    const __nv_bfloat16* __restrict__ Bhi, const __nv_bfloat16* __restrict__ Blo,
    float* __restrict__ C, float alpha, char* smem)
{
    const int tid  = threadIdx.x;
    const int wid  = tid >> 5;
    const int lane = tid & 31;
    const int m0 = blockIdx.y * 128;
    const int n0 = blockIdx.x * 64;
    const int wm0 = (wid & 3) * 32;     // warp m within block
    const int wn0 = (wid >> 2) * 32;    // warp n within block
    const uint32_t sb = smem_u32(smem);

    float acc[2][4][4];
#pragma unroll
    for (int mt = 0; mt < 2; mt++)
#pragma unroll
        for (int nt = 0; nt < 4; nt++)
#pragma unroll
            for (int i = 0; i < 4; i++) acc[mt][nt][i] = 0.f;

    load_stage(sb, 0, Ahi, Alo, Bhi, Blo, m0, n0, 0, tid);

    const int lr = lane & 15;
    const int lc = lane >> 4;

    for (int kt = 0; kt < 32; kt++) {
        if (kt < 31) {
            load_stage(sb, (kt + 1) & 1, Ahi, Alo, Bhi, Blo, m0, n0,
                       (kt + 1) * 32, tid);
            asm volatile("cp.async.wait_group 1;" ::: "memory");
        } else {
            asm volatile("cp.async.wait_group 0;" ::: "memory");
        }
        __syncthreads();

        const uint32_t st = sb + (kt & 1) * STG_BYTES;
#pragma unroll
        for (int ks = 0; ks < 2; ks++) {
            const int ch = ks * 2 + lc;
            uint32_t ahi[2][4], alo[2][4];
#pragma unroll
            for (int mt = 0; mt < 2; mt++) {
                int row = wm0 + mt * 16 + lr;
                ldsm4(ahi[mt][0], ahi[mt][1], ahi[mt][2], ahi[mt][3],
                      sw_addr(st + OFF_AHI, row, ch));
                ldsm4(alo[mt][0], alo[mt][1], alo[mt][2], alo[mt][3],
                      sw_addr(st + OFF_ALO, row, ch));
            }
            uint32_t bhi[4][2], blo[4][2];
#pragma unroll
            for (int ng = 0; ng < 2; ng++) {
                int row = wn0 + ng * 16 + lr;
                uint32_t t0, t1, t2, t3;
                ldsm4(t0, t1, t2, t3, sw_addr(st + OFF_BHI, row, ch));
                bhi[ng*2][0] = t0; bhi[ng*2+1][0] = t1;
                bhi[ng*2][1] = t2; bhi[ng*2+1][1] = t3;
                ldsm4(t0, t1, t2, t3, sw_addr(st + OFF_BLO, row, ch));
                blo[ng*2][0] = t0; blo[ng*2+1][0] = t1;
                blo[ng*2][1] = t2; blo[ng*2+1][1] = t3;
            }
#pragma unroll
            for (int mt = 0; mt < 2; mt++)
#pragma unroll
                for (int nt = 0; nt < 4; nt++) {
                    mma16816(acc[mt][nt], ahi[mt], bhi[nt]);
                    mma16816(acc[mt][nt], ahi[mt], blo[nt]);
                    mma16816(acc[mt][nt], alo[mt], bhi[nt]);
                }
        }
        __syncthreads();
    }

    // Epilogue: c0,c1 -> (m = l/4, n = 2(l%4)); c2,c3 -> (m = l/4 + 8)
    const int er = lane >> 2;
    const int ec = (lane & 3) << 1;
#pragma unroll
    for (int mt = 0; mt < 2; mt++)
#pragma unroll
        for (int nt = 0; nt < 4; nt++) {
            int row = m0 + wm0 + mt * 16 + er;
            int col = n0 + wn0 + nt * 8 + ec;
            float2 v0 = make_float2(acc[mt][nt][0] * alpha, acc[mt][nt][1] * alpha);
            float2 v1 = make_float2(acc[mt][nt][2] * alpha, acc[mt][nt][3] * alpha);
            *(float2*)(C + (size_t)row * DIMN + col)       = v0;
            *(float2*)(C + (size_t)(row + 8) * DIMN + col) = v1;
        }
}

__global__ __launch_bounds__(256) void gemm4_kernel()
{
    extern __shared__ char smem[];
    const int z = blockIdx.z;
    const __nv_bfloat16* Bhi = g_Whi + (size_t)z * DIMN * DIMN;
    const __nv_bfloat16* Blo = g_Wlo + (size_t)z * DIMN * DIMN;
    float* outs[4] = {g_q, g_k, g_v, g_g};
    float alpha = (z == 0) ? QSCALE : 1.f;
    gemm_body(g_xhi, g_xlo, Bhi, Blo, outs[z], alpha, smem);
}

__global__ __launch_bounds__(256) void gemmo_kernel(float* __restrict__ out)
{
    extern __shared__ char smem[];
    gemm_body(g_onhi, g_onlo, g_Whi + (size_t)4 * DIMN * DIMN,
              g_Wlo + (size_t)4 * DIMN * DIMN, out, 1.f, smem);
}

// ---------------------------------------------------------------------------
// Fused low-rank gate path: one block per row m.
//   Phase 1: t1[16] = x[m] @ Wgk1          (256 thr = 16 ksplit x 16 col)
//   Phase 2: gk[m][n] = logsigmoid(t1 @ Wgk2[:,n] + b[n]) / 16  (4 n per thr)
// ---------------------------------------------------------------------------
__global__ __launch_bounds__(256) void lowrank_gk_kernel(
    const float* __restrict__ x, const float* __restrict__ Wgk1,
    const float* __restrict__ Wgk2, const float* __restrict__ bgk2)
{
    const int m   = blockIdx.x;
    const int tid = threadIdx.x;
    const int ks  = tid >> 4;        // 0..15 (k segment of 64)
    const int c   = tid & 15;        // 0..15 (t1 column)

    __shared__ float sPart[16][17];
    __shared__ float sT1[16];

    const float* xr = x + (size_t)m * DIMN;
    float acc = 0.f;
    const int kb = ks * 64;
#pragma unroll 8
    for (int i = 0; i < 64; i++)
        acc = fmaf(xr[kb + i], Wgk1[(kb + i) * 16 + c], acc);
    sPart[ks][c] = acc;
    __syncthreads();

    if (tid < 16) {
        float s = 0.f;
#pragma unroll
        for (int j = 0; j < 16; j++) s += sPart[j][tid];
        sT1[tid] = s;
    }
    __syncthreads();

    float t1[16];
#pragma unroll
    for (int j = 0; j < 16; j++) t1[j] = sT1[j];

#pragma unroll
    for (int u = 0; u < 4; u++) {
        int n = u * 256 + tid;
        float a = bgk2[n];
#pragma unroll
        for (int j = 0; j < 16; j++)
            a = fmaf(t1[j], Wgk2[j * DIMN + n], a);
        float ls = fminf(a, 0.f) - log1pf(__expf(-fabsf(a)));
        g_gk[(size_t)m * DIMN + n] = ls * GNORM;
    }
}

// ---------------------------------------------------------------------------
// Chunked GLA
// ---------------------------------------------------------------------------
__device__ __forceinline__ int row_off(int b, int h, int t)
{
    return (((b * TT + t) * HH + h) << 7);
}

// prep: 512 threads = 128 ch x 4 t-segments of 16; smem prefix across segments
__global__ __launch_bounds__(512) void prep_kernel()
{
    const int bhc = blockIdx.x;
    const int bh  = bhc >> 3, c0 = bhc & 7;
    const int b   = bh >> 3,  h  = bh & 7;
    const int ch  = threadIdx.x & 127;
    const int tg  = threadIdx.x >> 7;          // 0..3
    const int tbase = c0 * CH + tg * 16;

    __shared__ float gsum[4][128];

    float loc[16];
    float acc = 0.f;
#pragma unroll
    for (int s = 0; s < 16; s++) {
        loc[s] = g_gk[row_off(b, h, tbase + s) + ch];
        acc += loc[s];
    }
    gsum[tg][ch] = acc;
    __syncthreads();

    float off = 0.f;
#pragma unroll
    for (int g = 0; g < 4; g++)
        if (g < tg) off += gsum[g][ch];
    float tot = gsum[0][ch] + gsum[1][ch] + gsum[2][ch] + gsum[3][ch];

    float bacc = off;
#pragma unroll 4
    for (int s = 0; s < 16; s++) {
        bacc += loc[s];
        int r = row_off(b, h, tbase + s) + ch;
        float q = g_q[r], k = g_k[r];
        g_qg[r] = q * __expf(bacc);
        g_kd[r] = k * __expf(-bacc);
        g_kr[r] = k * __expf(tot - bacc);
    }
    if (threadIdx.x < 128)
        g_dc[bhc * 128 + ch] = __expf(tot);
}

// chunk_kv: KV_c[128][128] = sum_s k~_s^T v_s
__global__ __launch_bounds__(256) void chunk_kv_kernel()
{
    const int bhc = blockIdx.x;
    const int bh  = bhc >> 3, c0 = bhc & 7;
    const int b   = bh >> 3,  h  = bh & 7;
    const int tid = threadIdx.x;
    const int tr  = tid >> 4, tc = tid & 15;
    const int kr0 = tr << 3, vc0 = tc << 3;
    const int tbase = c0 * CH;

    __shared__ float sK[16][128];
    __shared__ float sV[16][128];

    float acc[8][8];
#pragma unroll
    for (int i = 0; i < 8; i++)
#pragma unroll
        for (int j = 0; j < 8; j++) acc[i][j] = 0.f;

    for (int st = 0; st < 4; st++) {
#pragma unroll
        for (int u = 0; u < 2; u++) {
            int f  = tid + (u << 8);
            int sr = f >> 5;
            int sc = (f & 31) << 2;
            int r  = row_off(b, h, tbase + st * 16 + sr) + sc;
            *(float4*)&sK[sr][sc] = *(const float4*)(g_kr + r);
            *(float4*)&sV[sr][sc] = *(const float4*)(g_v + r);
        }
        __syncthreads();
#pragma unroll
        for (int ss = 0; ss < 16; ss++) {
            float4 k0 = *(const float4*)&sK[ss][kr0];
            float4 k1 = *(const float4*)&sK[ss][kr0 + 4];
            float4 v0 = *(const float4*)&sV[ss][vc0];
            float4 v1 = *(const float4*)&sV[ss][vc0 + 4];
            float kr[8] = {k0.x,k0.y,k0.z,k0.w,k1.x,k1.y,k1.z,k1.w};
            float vr[8] = {v0.x,v0.y,v0.z,v0.w,v1.x,v1.y,v1.z,v1.w};
#pragma unroll
            for (int i = 0; i < 8; i++)
#pragma unroll
                for (int j = 0; j < 8; j++)
                    acc[i][j] = fmaf(kr[i], vr[j], acc[i][j]);
        }
        __syncthreads();
    }

    float* dst = g_kv + (size_t)bhc * 16384;
#pragma unroll
    for (int i = 0; i < 8; i++) {
        *(float4*)(dst + (kr0 + i) * 128 + vc0)     = make_float4(acc[i][0],acc[i][1],acc[i][2],acc[i][3]);
        *(float4*)(dst + (kr0 + i) * 128 + vc0 + 4) = make_float4(acc[i][4],acc[i][5],acc[i][6],acc[i][7]);
    }
}

// state scan: parallel over (bh, v-group of 16); serial over 8 chunks.
__global__ __launch_bounds__(256) void state_scan_kernel()
{
    const int bh = blockIdx.x >> 3;
    const int vg = blockIdx.x & 7;
    const int tid = threadIdx.x;
    const int k    = tid >> 1;
    const int voff = vg * 16 + (tid & 1) * 8;

    float4 S0 = make_float4(0.f,0.f,0.f,0.f);
    float4 S1 = make_float4(0.f,0.f,0.f,0.f);

    for (int c = 0; c < NC; c++) {
        const int bhc = bh * NC + c;
        const size_t base = (size_t)bhc * 16384 + (size_t)k * 128 + voff;
        const float d = g_dc[bhc * 128 + k];
        *(float4*)(g_S + base)     = S0;
        *(float4*)(g_S + base + 4) = S1;
        float4 a = *(const float4*)(g_kv + base);
        float4 b = *(const float4*)(g_kv + base + 4);
        S0.x = fmaf(S0.x, d, a.x); S0.y = fmaf(S0.y, d, a.y);
        S0.z = fmaf(S0.z, d, a.z); S0.w = fmaf(S0.w, d, a.w);
        S1.x = fmaf(S1.x, d, b.x); S1.y = fmaf(S1.y, d, b.y);
        S1.z = fmaf(S1.z, d, b.z); S1.w = fmaf(S1.w, d, b.w);
    }
}

// chunk_out: o = q~ @ S_c + tril(q~ @ k^^T) @ V, fused gated RMSNorm -> g_on
__global__ __launch_bounds__(256) void chunk_out_kernel(
    const float* __restrict__ g_norm_w)
{
    const int bhc = blockIdx.x;
    const int bh  = bhc >> 3, c0 = bhc & 7;
    const int b   = bh >> 3,  h  = bh & 7;
    const int tid = threadIdx.x;
    const int tr  = tid >> 4, tc = tid & 15;
    const int t0  = tr << 2;
    const int v0  = tc << 3;
    const int tbase = c0 * CH;

    __shared__ float sQ [16][68];
    __shared__ float sKd[16][68];
    __shared__ float sS [16][128];
    __shared__ float sA [64][68];
    __shared__ float sV [16][128];

    float o[4][8];
    float a2[4][4];
#pragma unroll
    for (int i = 0; i < 4; i++) {
#pragma unroll
        for (int j = 0; j < 8; j++) o[i][j] = 0.f;
#pragma unroll
        for (int j = 0; j < 4; j++) a2[i][j] = 0.f;
    }

    const size_t Sbase = (size_t)bhc * 16384;

    for (int k0 = 0; k0 < 128; k0 += 16) {
        {
            int tt = tid >> 2;
            int c4 = (tid & 3) << 2;
            int r  = row_off(b, h, tbase + tt) + k0 + c4;
            float4 qv = *(const float4*)(g_qg + r);
            sQ[c4+0][tt] = qv.x; sQ[c4+1][tt] = qv.y;
            sQ[c4+2][tt] = qv.z; sQ[c4+3][tt] = qv.w;
            float4 kv = *(const float4*)(g_kd + r);
            sKd[c4+0][tt] = kv.x; sKd[c4+1][tt] = kv.y;
            sKd[c4+2][tt] = kv.z; sKd[c4+3][tt] = kv.w;
        }
#pragma unroll
        for (int u = 0; u < 2; u++) {
            int f  = tid + (u << 8);
            int sr = f >> 5;
            int sc = (f & 31) << 2;
            *(float4*)&sS[sr][sc] =
                *(const float4*)(g_S + Sbase + (k0 + sr) * 128 + sc);
        }
        __syncthreads();

#pragma unroll
        for (int kk = 0; kk < 16; kk++) {
            float4 q4  = *(const float4*)&sQ[kk][t0];
            float4 s0  = *(const float4*)&sS[kk][v0];
            float4 s1  = *(const float4*)&sS[kk][v0 + 4];
            float4 kd4 = *(const float4*)&sKd[kk][tc << 2];
            float qr[4] = {q4.x, q4.y, q4.z, q4.w};
            float sr_[8] = {s0.x,s0.y,s0.z,s0.w,s1.x,s1.y,s1.z,s1.w};
            float kr[4] = {kd4.x,kd4.y,kd4.z,kd4.w};
#pragma unroll
            for (int i = 0; i < 4; i++) {
#pragma unroll
                for (int j = 0; j < 8; j++)
                    o[i][j] = fmaf(qr[i], sr_[j], o[i][j]);
#pragma unroll
                for (int j = 0; j < 4; j++)
                    a2[i][j] = fmaf(qr[i], kr[j], a2[i][j]);
            }
        }
        __syncthreads();
    }

#pragma unroll
    for (int i = 0; i < 4; i++) {
        int t = t0 + i;
#pragma unroll
        for (int j = 0; j < 4; j++) {
            int s = (tc << 2) + j;
            sA[t][s] = (s <= t) ? a2[i][j] : 0.f;
        }
    }
    __syncthreads();

    for (int st = 0; st < 4; st++) {
#pragma unroll
        for (int u = 0; u < 2; u++) {
            int f  = tid + (u << 8);
            int sr = f >> 5;
            int sc = (f & 31) << 2;
            int r  = row_off(b, h, tbase + st * 16 + sr) + sc;
            *(float4*)&sV[sr][sc] = *(const float4*)(g_v + r);
        }
        __syncthreads();
#pragma unroll
        for (int ss = 0; ss < 16; ss++) {
            int s = st * 16 + ss;
            float a[4];
#pragma unroll
            for (int i = 0; i < 4; i++) a[i] = sA[t0 + i][s];
            float4 vv0 = *(const float4*)&sV[ss][v0];
            float4 vv1 = *(const float4*)&sV[ss][v0 + 4];
            float vr[8] = {vv0.x,vv0.y,vv0.z,vv0.w,vv1.x,vv1.y,vv1.z,vv1.w};
#pragma unroll
            for (int i = 0; i < 4; i++)
#pragma unroll
                for (int j = 0; j < 8; j++)
                    o[i][j] = fmaf(a[i], vr[j], o[i][j]);
        }
        __syncthreads();
    }

    float4 w0 = *(const float4*)(g_norm_w + v0);
    float4 w1 = *(const float4*)(g_norm_w + v0 + 4);
    float wr[8] = {w0.x,w0.y,w0.z,w0.w,w1.x,w1.y,w1.z,w1.w};

#pragma unroll
    for (int i = 0; i < 4; i++) {
        float ss = 0.f;
#pragma unroll
        for (int j = 0; j < 8; j++) ss = fmaf(o[i][j], o[i][j], ss);
#pragma unroll
        for (int off = 1; off < 16; off <<= 1)
            ss += __shfl_xor_sync(0xffffffffu, ss, off);
        float rms = rsqrtf(ss * (1.f / 128.f) + 1e-5f);

        int r = row_off(b, h, tbase + t0 + i);
        float4 gg0 = *(const float4*)(g_g + r + v0);
        float4 gg1 = *(const float4*)(g_g + r + v0 + 4);
        float gr[8] = {gg0.x,gg0.y,gg0.z,gg0.w,gg1.x,gg1.y,gg1.z,gg1.w};
        float on[8];
#pragma unroll
        for (int j = 0; j < 8; j++) {
            float gvv = gr[j];
            float sw  = gvv / (1.f + __expf(-gvv));
            on[j] = o[i][j] * rms * wr[j] * sw;
        }
        *(float4*)(g_on + r + v0)     = make_float4(on[0],on[1],on[2],on[3]);
        *(float4*)(g_on + r + v0 + 4) = make_float4(on[4],on[5],on[6],on[7]);
    }
}

// ---------------------------------------------------------------------------
extern "C" void kernel_launch(void* const* d_in, const int* in_sizes, int n_in,
                              void* d_out, int out_size)
{
    const float* x        = (const float*)d_in[0];
    const float* Wq       = (const float*)d_in[1];
    const float* Wk       = (const float*)d_in[2];
    const float* Wv       = (const float*)d_in[3];
    const float* Wg       = (const float*)d_in[4];
    const float* Wgk1     = (const float*)d_in[5];
    const float* Wgk2     = (const float*)d_in[6];
    const float* bgk2     = (const float*)d_in[7];
    const float* g_norm_w = (const float*)d_in[8];
    const float* Wo       = (const float*)d_in[9];
    float* out = (float*)d_out;

    conv_w_kernel<<<dim3(32, 32, 5), dim3(256)>>>(Wq, Wk, Wv, Wg, Wo);
    conv_x_kernel<<<1024, 256>>>(x);
    gemm4_kernel<<<dim3(16, 8, 4), 256, SMEM_GEMM>>>();
    lowrank_gk_kernel<<<1024, 256>>>(x, Wgk1, Wgk2, bgk2);
    prep_kernel<<<128, 512>>>();
    chunk_kv_kernel<<<128, 256>>>();
    state_scan_kernel<<<128, 256>>>();
    chunk_out_kernel<<<128, 256>>>(g_norm_w);
    conv_on_kernel<<<1024, 256>>>();
    gemmo_kernel<<<dim3(16, 8), 256, SMEM_GEMM>>>(out);
}